// round 14
// baseline (speedup 1.0000x reference)
#include <cuda_runtime.h>
#include <cuda_fp16.h>
#include <cstdint>

// TriangleMultiplicativeUpdate (outgoing), B=1, N=512, C=128. fp16 mma m16n8k16.
// kW: weights -> [n][k] half.
// kP: PERSISTENT (296 CTAs); CTA parity picks a/b pair; weights resident in smem.
// kE: 128 per-channel GEMMs, 128x128 tiles, 2 CTAs/SM, cp.async double-buffered.
// kF: fused dual GEMM: out = (LN(X)@w_z + b_z) * sigmoid(LN(z)@w_g + b_g).

#define NPOS 262144
#define SZS  136          // smem row stride in halfs
#define KES  72           // kE smem row stride in halfs

__device__ __half d_Wt[6 * 16384];           // [w][n][k]
__device__ __half d_Ah[(size_t)128 * NPOS];  // [c][i*512+k]
__device__ __half d_Bh[(size_t)128 * NPOS];
__device__ __half d_Xh[(size_t)128 * NPOS];  // [c][i*512+j]

__device__ __forceinline__ float sigf(float x) { return 1.0f / (1.0f + __expf(-x)); }

__device__ __forceinline__ void mma16(float* d, const unsigned* a, const unsigned* b) {
    asm volatile(
        "mma.sync.aligned.m16n8k16.row.col.f32.f16.f16.f32 "
        "{%0,%1,%2,%3}, {%4,%5,%6,%7}, {%8,%9}, {%0,%1,%2,%3};\n"
        : "+f"(d[0]), "+f"(d[1]), "+f"(d[2]), "+f"(d[3])
        : "r"(a[0]), "r"(a[1]), "r"(a[2]), "r"(a[3]), "r"(b[0]), "r"(b[1]));
}

__device__ __forceinline__ void ldsm4(unsigned* r, const __half* p) {
    unsigned addr = (unsigned)__cvta_generic_to_shared(p);
    asm volatile("ldmatrix.sync.aligned.m8n8.x4.shared.b16 {%0,%1,%2,%3}, [%4];"
                 : "=r"(r[0]), "=r"(r[1]), "=r"(r[2]), "=r"(r[3]) : "r"(addr));
}

__device__ __forceinline__ void stsm4t(__half* p, unsigned r0, unsigned r1,
                                       unsigned r2, unsigned r3) {
    unsigned addr = (unsigned)__cvta_generic_to_shared(p);
    asm volatile("stmatrix.sync.aligned.m8n8.x4.trans.shared.b16 [%0], {%1,%2,%3,%4};"
                 :: "r"(addr), "r"(r0), "r"(r1), "r"(r2), "r"(r3) : "memory");
}

__device__ __forceinline__ void cp16(void* s, const void* g) {
    unsigned sa = (unsigned)__cvta_generic_to_shared(s);
    asm volatile("cp.async.cg.shared.global [%0], [%1], 16;" :: "r"(sa), "l"(g));
}
#define CPCOMMIT() asm volatile("cp.async.commit_group;")
#define CPWAIT(n)  asm volatile("cp.async.wait_group %0;" :: "n"(n))

// ---------------- kW: weight transpose+convert ------------------------------
__global__ __launch_bounds__(256) void kW(
    const float* __restrict__ w_ag, const float* __restrict__ w_ap,
    const float* __restrict__ w_bg, const float* __restrict__ w_bp,
    const float* __restrict__ w_g,  const float* __restrict__ w_z)
{
    __shared__ float s[128 * 132];
    const float* srcs[6] = {w_ag, w_ap, w_bg, w_bp, w_g, w_z};
    const float* w = srcs[blockIdx.x];
    const int t = threadIdx.x;
    #pragma unroll
    for (int l = 0; l < 64; l++) {
        const int idx = t + l * 256;
        s[(idx >> 7) * 132 + (idx & 127)] = w[idx];   // [k][n]
    }
    __syncthreads();
    __half* dst = d_Wt + blockIdx.x * 16384;
    #pragma unroll
    for (int l = 0; l < 64; l++) {
        const int idx = t + l * 256;                  // idx = n*128 + k
        dst[idx] = __float2half_rn(s[(idx & 127) * 132 + (idx >> 7)]);
    }
}

// ---------------- shared helpers ---------------------------------------------
__device__ __forceinline__ void prefW(__half* buf, const __half* __restrict__ wt, int t) {
    #pragma unroll
    for (int l = 0; l < 8; l++) {
        const int idx = t + l * 256;                 // 2048 uint4
        const int n = idx >> 4, k8 = (idx & 15) * 8;
        cp16(&buf[n * SZS + k8], &wt[n * 128 + k8]);
    }
    CPCOMMIT();
}

__device__ __forceinline__ void lnrows64(const float* __restrict__ zsrc, __half* sdst,
                                         const float* __restrict__ g,
                                         const float* __restrict__ b,
                                         int warp, int lane) {
    const float g0 = g[lane], g1 = g[lane + 32], g2 = g[lane + 64], g3 = g[lane + 96];
    const float b0 = b[lane], b1 = b[lane + 32], b2 = b[lane + 64], b3 = b[lane + 96];
    #pragma unroll 1
    for (int rr = 0; rr < 8; rr++) {
        const int r = warp * 8 + rr;
        const float* zr = zsrc + (size_t)r * 128;
        float v0 = zr[lane], v1 = zr[lane + 32], v2 = zr[lane + 64], v3 = zr[lane + 96];
        float sm = (v0 + v1) + (v2 + v3);
        float sq = fmaf(v0, v0, fmaf(v1, v1, fmaf(v2, v2, v3 * v3)));
        #pragma unroll
        for (int o = 16; o > 0; o >>= 1) {
            sm += __shfl_xor_sync(0xffffffffu, sm, o);
            sq += __shfl_xor_sync(0xffffffffu, sq, o);
        }
        const float mean = sm * 0.0078125f;
        const float var  = fmaf(-mean, mean, sq * 0.0078125f);
        const float rs   = rsqrtf(var + 1e-5f);
        sdst[r * SZS + lane]      = __float2half_rn(fmaf((v0 - mean) * rs, g0, b0));
        sdst[r * SZS + lane + 32] = __float2half_rn(fmaf((v1 - mean) * rs, g1, b1));
        sdst[r * SZS + lane + 64] = __float2half_rn(fmaf((v2 - mean) * rs, g2, b2));
        sdst[r * SZS + lane + 96] = __float2half_rn(fmaf((v3 - mean) * rs, g3, b3));
    }
}

// 64x128 GEMM: 8 warps in 2(M) x 4(N), warp tile 32x32.
__device__ __forceinline__ void gemmC(
    const __half* sW, const __half* sZ, float acc[2][4][4],
    int wy, int lw, int aRow, int aCol, int bRow, int bCol)
{
    #pragma unroll
    for (int k0 = 0; k0 < 128; k0 += 16) {
        unsigned af[2][4], bf[2][4];
        #pragma unroll
        for (int mt = 0; mt < 2; mt++)
            ldsm4(af[mt], sZ + (wy * 32 + mt * 16 + aRow) * SZS + k0 + aCol);
        #pragma unroll
        for (int p = 0; p < 2; p++)
            ldsm4(bf[p], sW + (lw * 32 + p * 16 + bRow) * SZS + k0 + bCol);
        #pragma unroll
        for (int mt = 0; mt < 2; mt++)
            #pragma unroll
            for (int nt = 0; nt < 4; nt++)
                mma16(acc[mt][nt], af[mt], &bf[nt >> 1][(nt & 1) * 2]);
    }
}

// ---------------- kP: persistent, pair per CTA parity ------------------------
#define KP_CTAS 296
__global__ __launch_bounds__(256, 2) void kP(
    const float* __restrict__ z,    const float* __restrict__ mask,
    const float* __restrict__ b_ag, const float* __restrict__ b_ap,
    const float* __restrict__ b_bg, const float* __restrict__ b_bp,
    const float* __restrict__ lng,  const float* __restrict__ lnb)
{
    extern __shared__ __half sh[];
    __half* sZ  = sh;                             // [64][SZS]
    __half* sW0 = sh + 64 * SZS;                  // [128][SZS] gate weights (resident)
    __half* sW1 = sh + 64 * SZS + 128 * SZS;      // [128][SZS] proj weights (resident)
    __half* sSt = sh + 64 * SZS + 2 * 128 * SZS;  // [64][SZS]
    const int t = threadIdx.x, lane = t & 31, warp = t >> 5;
    const int wy = warp >> 2, lw = warp & 3;

    const int pair = blockIdx.x & 1;
    const float* biasG = pair ? b_bg : b_ag;
    const float* biasP = pair ? b_bp : b_ap;
    __half* plane = pair ? d_Bh : d_Ah;

    // resident weights, loaded once
    prefW(sW0, d_Wt + (pair * 2 + 0) * 16384, t);
    prefW(sW1, d_Wt + (pair * 2 + 1) * 16384, t);
    CPWAIT(0);

    const int aRow = (lane & 7) + ((lane >> 3) & 1) * 8;
    const int aCol = (lane >> 4) * 8;
    const int bRow = (lane & 7) + ((lane >> 4) & 1) * 8;
    const int bCol = ((lane >> 3) & 1) * 8;
    const int rB = wy * 32 + (lane >> 2);
    const int cB = lw * 32 + (lane & 3) * 2;

    #pragma unroll 1
    for (int item = blockIdx.x >> 1; item < 4096; item += KP_CTAS / 2) {
        const int pos0 = item * 64;
        __syncthreads();                 // sZ/sSt free (prev iter done)
        lnrows64(z + (size_t)pos0 * 128, sZ, lng, lnb, warp, lane);
        __syncthreads();

        float accg[2][4][4] = {};
        gemmC(sW0, sZ, accg, wy, lw, aRow, aCol, bRow, bCol);
        float accp[2][4][4] = {};
        gemmC(sW1, sZ, accp, wy, lw, aRow, aCol, bRow, bCol);

        #pragma unroll
        for (int mt = 0; mt < 2; mt++) {
            const int r = rB + mt * 16;
            const float m0 = mask[pos0 + r], m1 = mask[pos0 + r + 8];
            #pragma unroll
            for (int nt = 0; nt < 4; nt++) {
                const int c = cB + nt * 8;
                const float bg0 = biasG[c], bg1 = biasG[c + 1];
                const float bp0 = biasP[c], bp1 = biasP[c + 1];
                *(__half2*)&sSt[r * SZS + c] = __floats2half2_rn(
                    m0 * sigf(accg[mt][nt][0] + bg0) * (accp[mt][nt][0] + bp0),
                    m0 * sigf(accg[mt][nt][1] + bg1) * (accp[mt][nt][1] + bp1));
                *(__half2*)&sSt[(r + 8) * SZS + c] = __floats2half2_rn(
                    m1 * sigf(accg[mt][nt][2] + bg0) * (accp[mt][nt][2] + bp0),
                    m1 * sigf(accg[mt][nt][3] + bg1) * (accp[mt][nt][3] + bp1));
            }
        }
        __syncthreads();
        // transposed flush: [p][c] -> plane[c][pos0+p]
        #pragma unroll
        for (int l = 0; l < 32; l++) {
            const int idx = t + l * 256;
            const int c = idx >> 6, p = idx & 63;
            plane[(size_t)c * NPOS + pos0 + p] = sSt[p * SZS + c];
        }
    }
}

// ---------------- kE: per-channel GEMM, 128x128 tile, 2 CTAs/SM --------------
#define KE_STAGEH 18432                       // halfs per stage: (128+128)*72
#define KE_SMEM   (2 * KE_STAGEH * 2)         // 73728 bytes

__global__ __launch_bounds__(256, 2) void kE()
{
    extern __shared__ __half she[];
    const int t = threadIdx.x, lane = t & 31, warp = t >> 5;
    const int wy = warp >> 2, lw = warp & 3;
    const int j0 = blockIdx.x * 128, i0 = blockIdx.y * 128, ch = blockIdx.z;
    const __half* __restrict__ Ap = d_Ah + (size_t)ch * NPOS;
    const __half* __restrict__ Bp = d_Bh + (size_t)ch * NPOS;

    const int aRow = (lane & 7) + ((lane >> 3) & 1) * 8;
    const int aCol = (lane >> 4) * 8;
    const int bRow = (lane & 7) + ((lane >> 4) & 1) * 8;
    const int bCol = ((lane >> 3) & 1) * 8;

    const int lr = t >> 3, lk8 = (t & 7) * 8;

    auto load_chunk = [&](int c, int stage) {
        __half* sA = she + stage * KE_STAGEH;
        __half* sB = sA + 128 * KES;
        const int kt = c * 64;
        #pragma unroll
        for (int l = 0; l < 4; l++) {
            const int r = lr + l * 32;
            cp16(&sA[r * KES + lk8], &Ap[(size_t)(i0 + r) * 512 + kt + lk8]);
        }
        #pragma unroll
        for (int l = 0; l < 4; l++) {
            const int r = lr + l * 32;
            cp16(&sB[r * KES + lk8], &Bp[(size_t)(j0 + r) * 512 + kt + lk8]);
        }
        CPCOMMIT();
    };

    float acc[4][4][4] = {};

    load_chunk(0, 0);

    #pragma unroll 1
    for (int s = 0; s < 8; s++) {
        if (s < 7) {
            load_chunk(s + 1, (s + 1) & 1);
            CPWAIT(1);
        } else {
            CPWAIT(0);
        }
        __syncthreads();
        const __half* bA = she + (s & 1) * KE_STAGEH;
        const __half* bB = bA + 128 * KES;
        #pragma unroll
        for (int kk = 0; kk < 64; kk += 16) {
            unsigned af[4][4], bf[2][4];
            #pragma unroll
            for (int mt = 0; mt < 4; mt++)
                ldsm4(af[mt], bA + (wy * 64 + mt * 16 + aRow) * KES + kk + aCol);
            #pragma unroll
            for (int p = 0; p < 2; p++)
                ldsm4(bf[p], bB + (lw * 32 + p * 16 + bRow) * KES + kk + bCol);
            #pragma unroll
            for (int mt = 0; mt < 4; mt++)
                #pragma unroll
                for (int nt = 0; nt < 4; nt++)
                    mma16(acc[mt][nt], af[mt], &bf[nt >> 1][(nt & 1) * 2]);
        }
        __syncthreads();
    }

    __half* sSt = she;
    #pragma unroll
    for (int mt = 0; mt < 4; mt++)
        #pragma unroll
        for (int nt = 0; nt < 4; nt++) {
            const int r = wy * 64 + mt * 16 + (lane >> 2);
            const int c = lw * 32 + nt * 8 + (lane & 3) * 2;
            *(__half2*)&sSt[r * SZS + c]       = __floats2half2_rn(acc[mt][nt][0], acc[mt][nt][1]);
            *(__half2*)&sSt[(r + 8) * SZS + c] = __floats2half2_rn(acc[mt][nt][2], acc[mt][nt][3]);
        }
    __syncthreads();
    __half* Xp = d_Xh + (size_t)ch * NPOS;
    #pragma unroll
    for (int l = 0; l < 8; l++) {
        const int idx = t + l * 256;
        const int r = idx >> 4, c16 = idx & 15;
        *(uint4*)&Xp[(size_t)(i0 + r) * 512 + j0 + c16 * 8] = *(const uint4*)&sSt[r * SZS + c16 * 8];
    }
}

// ---------------- kF: fused dual GEMM ----------------------------------------
__global__ __launch_bounds__(256, 3) void kF(
    const float* __restrict__ z,
    const float* __restrict__ lnig, const float* __restrict__ lnib,
    const float* __restrict__ lnog, const float* __restrict__ lnob,
    const float* __restrict__ b_z,  const float* __restrict__ b_g,
    float* __restrict__ out)
{
    extern __shared__ __half shf[];
    __half* sX = shf;                 // [64][SZS]
    __half* sG = shf + 64 * SZS;      // [64][SZS]
    __half* sW = shf + 128 * SZS;     // [128][SZS]
    const int t = threadIdx.x, lane = t & 31, warp = t >> 5;
    const int wy = warp >> 2, lw = warp & 3;
    const int pos0 = blockIdx.x * 64;
    const int c2 = lane * 2;

    prefW(sW, d_Wt + 4 * 16384, t);   // w_g

    {
        const int cl = lane >> 2, j = lane & 3;
        const int srow = 8 * (lane >> 3) + (lane & 7);
        #pragma unroll
        for (int it = 0; it < 4; it++) {
            const int tile = warp * 4 + it;
            const int cg = tile >> 1;
            const int pg = tile & 1;
            const __half* src = d_Xh + (size_t)(cg * 8 + cl) * NPOS + pos0 + pg * 32 + 2 * j;
            const unsigned r0 = *(const unsigned*)(src);
            const unsigned r1 = *(const unsigned*)(src + 8);
            const unsigned r2 = *(const unsigned*)(src + 16);
            const unsigned r3 = *(const unsigned*)(src + 24);
            stsm4t(sX + (pg * 32 + srow) * SZS + cg * 8, r0, r1, r2, r3);
        }
    }

    // LN(z) -> sG
    {
        const float g0 = lnig[c2], g1 = lnig[c2 + 1], g2 = lnig[c2 + 64], g3 = lnig[c2 + 65];
        const float bb0 = lnib[c2], bb1 = lnib[c2 + 1], bb2 = lnib[c2 + 64], bb3 = lnib[c2 + 65];
        #pragma unroll 1
        for (int rr = 0; rr < 8; rr++) {
            const int r = warp * 8 + rr;
            const float* zr = z + (size_t)(pos0 + r) * 128;
            const float2 v01 = *(const float2*)&zr[c2];
            const float2 v23 = *(const float2*)&zr[c2 + 64];
            float sm = (v01.x + v01.y) + (v23.x + v23.y);
            float sq = fmaf(v01.x, v01.x, fmaf(v01.y, v01.y, fmaf(v23.x, v23.x, v23.y * v23.y)));
            #pragma unroll
            for (int o = 16; o > 0; o >>= 1) {
                sm += __shfl_xor_sync(0xffffffffu, sm, o);
                sq += __shfl_xor_sync(0xffffffffu, sq, o);
            }
            const float mean = sm * 0.0078125f;
            const float var  = fmaf(-mean, mean, sq * 0.0078125f);
            const float rs   = rsqrtf(var + 1e-5f);
            *(__half2*)&sG[r * SZS + c2] = __floats2half2_rn(
                fmaf((v01.x - mean) * rs, g0, bb0), fmaf((v01.y - mean) * rs, g1, bb1));
            *(__half2*)&sG[r * SZS + c2 + 64] = __floats2half2_rn(
                fmaf((v23.x - mean) * rs, g2, bb2), fmaf((v23.y - mean) * rs, g3, bb3));
        }
    }
    CPWAIT(0);
    __syncthreads();

    const int aRow = (lane & 7) + ((lane >> 3) & 1) * 8;
    const int aCol = (lane >> 4) * 8;
    const int bRow = (lane & 7) + ((lane >> 4) & 1) * 8;
    const int bCol = ((lane >> 3) & 1) * 8;
    const int rB = wy * 32 + (lane >> 2);
    const int cB = lw * 32 + (lane & 3) * 2;

    float accg[2][4][4] = {};
    gemmC(sW, sG, accg, wy, lw, aRow, aCol, bRow, bCol);
    __syncthreads();

    prefW(sW, d_Wt + 5 * 16384, t);   // w_z

    #pragma unroll
    for (int mt = 0; mt < 2; mt++)
        #pragma unroll
        for (int nt = 0; nt < 4; nt++) {
            const int r = rB + mt * 16;
            const int c = cB + nt * 8;
            const float bg0 = b_g[c], bg1 = b_g[c + 1];
            *(__half2*)&sG[r * SZS + c] = __floats2half2_rn(
                sigf(accg[mt][nt][0] + bg0), sigf(accg[mt][nt][1] + bg1));
            *(__half2*)&sG[(r + 8) * SZS + c] = __floats2half2_rn(
                sigf(accg[mt][nt][2] + bg0), sigf(accg[mt][nt][3] + bg1));
        }

    // LN(X) in place
    {
        const float g0 = lnog[c2], g1 = lnog[c2 + 1], g2 = lnog[c2 + 64], g3 = lnog[c2 + 65];
        const float bb0 = lnob[c2], bb1 = lnob[c2 + 1], bb2 = lnob[c2 + 64], bb3 = lnob[c2 + 65];
        #pragma unroll 1
        for (int rr = 0; rr < 8; rr++) {
            const int r = warp * 8 + rr;
            __half* row = sX + r * SZS;
            const float2 v01 = __half22float2(*(__half2*)&row[c2]);
            const float2 v23 = __half22float2(*(__half2*)&row[c2 + 64]);
            float sm = (v01.x + v01.y) + (v23.x + v23.y);
            float sq = fmaf(v01.x, v01.x, fmaf(v01.y, v01.y, fmaf(v23.x, v23.x, v23.y * v23.y)));
            #pragma unroll
            for (int o = 16; o > 0; o >>= 1) {
                sm += __shfl_xor_sync(0xffffffffu, sm, o);
                sq += __shfl_xor_sync(0xffffffffu, sq, o);
            }
            const float mean = sm * 0.0078125f;
            const float var  = fmaf(-mean, mean, sq * 0.0078125f);
            const float rs   = rsqrtf(var + 1e-5f);
            *(__half2*)&row[c2] = __floats2half2_rn(
                fmaf((v01.x - mean) * rs, g0, bb0), fmaf((v01.y - mean) * rs, g1, bb1));
            *(__half2*)&row[c2 + 64] = __floats2half2_rn(
                fmaf((v23.x - mean) * rs, g2, bb2), fmaf((v23.y - mean) * rs, g3, bb3));
        }
    }
    CPWAIT(0);
    __syncthreads();

    float accx[2][4][4] = {};
    gemmC(sW, sX, accx, wy, lw, aRow, aCol, bRow, bCol);

    #pragma unroll
    for (int mt = 0; mt < 2; mt++)
        #pragma unroll
        for (int nt = 0; nt < 4; nt++) {
            const int r = rB + mt * 16;
            const int c0 = cB + nt * 8;
            const float bz0 = b_z[c0], bz1 = b_z[c0 + 1];
            const size_t p0 = (size_t)(pos0 + r) * 128 + c0;
            const size_t p1 = (size_t)(pos0 + r + 8) * 128 + c0;
            const float2 g0 = __half22float2(*(const __half2*)&sG[r * SZS + c0]);
            const float2 g1 = __half22float2(*(const __half2*)&sG[(r + 8) * SZS + c0]);
            *(float2*)&out[p0] = make_float2((accx[mt][nt][0] + bz0) * g0.x,
                                             (accx[mt][nt][1] + bz1) * g0.y);
            *(float2*)&out[p1] = make_float2((accx[mt][nt][2] + bz0) * g1.x,
                                             (accx[mt][nt][3] + bz1) * g1.y);
        }
}

extern "C" void kernel_launch(void* const* d_in, const int* in_sizes, int n_in,
                              void* d_out, int out_size)
{
    const float* z        = (const float*)d_in[0];
    const float* mask     = (const float*)d_in[1];
    const float* w_ag     = (const float*)d_in[2];
    const float* b_ag     = (const float*)d_in[3];
    const float* w_ap     = (const float*)d_in[4];
    const float* b_ap     = (const float*)d_in[5];
    const float* w_bg     = (const float*)d_in[6];
    const float* b_bg     = (const float*)d_in[7];
    const float* w_bp     = (const float*)d_in[8];
    const float* b_bp     = (const float*)d_in[9];
    const float* w_g      = (const float*)d_in[10];
    const float* b_g      = (const float*)d_in[11];
    const float* w_z      = (const float*)d_in[12];
    const float* b_z      = (const float*)d_in[13];
    const float* ln_in_g  = (const float*)d_in[14];
    const float* ln_in_b  = (const float*)d_in[15];
    const float* ln_out_g = (const float*)d_in[16];
    const float* ln_out_b = (const float*)d_in[17];

    const int KP_SMEM = (64 + 2 * 128 + 64) * SZS * 2;   // 104448
    const int KF_SMEM = (64 + 64 + 128) * SZS * 2;       // 69632
    cudaFuncSetAttribute(kP, cudaFuncAttributeMaxDynamicSharedMemorySize, KP_SMEM);
    cudaFuncSetAttribute(kE, cudaFuncAttributeMaxDynamicSharedMemorySize, KE_SMEM);
    cudaFuncSetAttribute(kF, cudaFuncAttributeMaxDynamicSharedMemorySize, KF_SMEM);

    kW<<<6, 256>>>(w_ag, w_ap, w_bg, w_bp, w_g, w_z);
    kP<<<KP_CTAS, 256, KP_SMEM>>>(z, mask, b_ag, b_ap, b_bg, b_bp, ln_in_g, ln_in_b);
    kE<<<dim3(4, 4, 128), 256, KE_SMEM>>>();
    kF<<<4096, 256, KF_SMEM>>>(z, ln_in_g, ln_in_b, ln_out_g, ln_out_b, b_z, b_g, (float*)d_out);
}

// round 15
// speedup vs baseline: 1.1733x; 1.1733x over previous
#include <cuda_runtime.h>
#include <cuda_fp16.h>
#include <cstdint>

// TriangleMultiplicativeUpdate (outgoing), B=1, N=512, C=128. fp16 mma m16n8k16.
// kW: weights -> [n][k] half.
// kP: LN + 4 projections -> half planes d_Ah/d_Bh, plus LN(z) -> d_Znh.
// kE: 128 per-channel GEMMs, 128x128 tiles, 2 CTAs/SM, cp.async double-buffered.
// kF: fused dual GEMM, gate input loaded from d_Znh (no LN recompute).

#define NPOS 262144
#define SZS  136          // smem row stride in halfs
#define KES  72           // kE smem row stride in halfs

__device__ __half d_Wt[6 * 16384];           // [w][n][k]
__device__ __half d_Ah[(size_t)128 * NPOS];  // [c][i*512+k]
__device__ __half d_Bh[(size_t)128 * NPOS];
__device__ __half d_Xh[(size_t)128 * NPOS];  // [c][i*512+j]
__device__ __half d_Znh[(size_t)NPOS * 128]; // [pos][c]  LN(z) in half

__device__ __forceinline__ float sigf(float x) { return 1.0f / (1.0f + __expf(-x)); }

__device__ __forceinline__ void mma16(float* d, const unsigned* a, const unsigned* b) {
    asm volatile(
        "mma.sync.aligned.m16n8k16.row.col.f32.f16.f16.f32 "
        "{%0,%1,%2,%3}, {%4,%5,%6,%7}, {%8,%9}, {%0,%1,%2,%3};\n"
        : "+f"(d[0]), "+f"(d[1]), "+f"(d[2]), "+f"(d[3])
        : "r"(a[0]), "r"(a[1]), "r"(a[2]), "r"(a[3]), "r"(b[0]), "r"(b[1]));
}

__device__ __forceinline__ void ldsm4(unsigned* r, const __half* p) {
    unsigned addr = (unsigned)__cvta_generic_to_shared(p);
    asm volatile("ldmatrix.sync.aligned.m8n8.x4.shared.b16 {%0,%1,%2,%3}, [%4];"
                 : "=r"(r[0]), "=r"(r[1]), "=r"(r[2]), "=r"(r[3]) : "r"(addr));
}

__device__ __forceinline__ void stsm4t(__half* p, unsigned r0, unsigned r1,
                                       unsigned r2, unsigned r3) {
    unsigned addr = (unsigned)__cvta_generic_to_shared(p);
    asm volatile("stmatrix.sync.aligned.m8n8.x4.trans.shared.b16 [%0], {%1,%2,%3,%4};"
                 :: "r"(addr), "r"(r0), "r"(r1), "r"(r2), "r"(r3) : "memory");
}

__device__ __forceinline__ void cp16(void* s, const void* g) {
    unsigned sa = (unsigned)__cvta_generic_to_shared(s);
    asm volatile("cp.async.cg.shared.global [%0], [%1], 16;" :: "r"(sa), "l"(g));
}
#define CPCOMMIT() asm volatile("cp.async.commit_group;")
#define CPWAIT(n)  asm volatile("cp.async.wait_group %0;" :: "n"(n))

// ---------------- kW: weight transpose+convert ------------------------------
__global__ __launch_bounds__(256) void kW(
    const float* __restrict__ w_ag, const float* __restrict__ w_ap,
    const float* __restrict__ w_bg, const float* __restrict__ w_bp,
    const float* __restrict__ w_g,  const float* __restrict__ w_z)
{
    __shared__ float s[128 * 132];
    const float* srcs[6] = {w_ag, w_ap, w_bg, w_bp, w_g, w_z};
    const float* w = srcs[blockIdx.x];
    const int t = threadIdx.x;
    #pragma unroll
    for (int l = 0; l < 64; l++) {
        const int idx = t + l * 256;
        s[(idx >> 7) * 132 + (idx & 127)] = w[idx];   // [k][n]
    }
    __syncthreads();
    __half* dst = d_Wt + blockIdx.x * 16384;
    #pragma unroll
    for (int l = 0; l < 64; l++) {
        const int idx = t + l * 256;                  // idx = n*128 + k
        dst[idx] = __float2half_rn(s[(idx & 127) * 132 + (idx >> 7)]);
    }
}

// ---------------- shared helpers ---------------------------------------------
__device__ __forceinline__ void prefW(__half* buf, const __half* __restrict__ wt, int t) {
    #pragma unroll
    for (int l = 0; l < 8; l++) {
        const int idx = t + l * 256;                 // 2048 uint4
        const int n = idx >> 4, k8 = (idx & 15) * 8;
        cp16(&buf[n * SZS + k8], &wt[n * 128 + k8]);
    }
    CPCOMMIT();
}

__device__ __forceinline__ void lnrows64(const float* __restrict__ zsrc, __half* sdst,
                                         const float* __restrict__ g,
                                         const float* __restrict__ b,
                                         int warp, int lane) {
    const float g0 = g[lane], g1 = g[lane + 32], g2 = g[lane + 64], g3 = g[lane + 96];
    const float b0 = b[lane], b1 = b[lane + 32], b2 = b[lane + 64], b3 = b[lane + 96];
    #pragma unroll 1
    for (int rr = 0; rr < 8; rr++) {
        const int r = warp * 8 + rr;
        const float* zr = zsrc + (size_t)r * 128;
        float v0 = zr[lane], v1 = zr[lane + 32], v2 = zr[lane + 64], v3 = zr[lane + 96];
        float sm = (v0 + v1) + (v2 + v3);
        float sq = fmaf(v0, v0, fmaf(v1, v1, fmaf(v2, v2, v3 * v3)));
        #pragma unroll
        for (int o = 16; o > 0; o >>= 1) {
            sm += __shfl_xor_sync(0xffffffffu, sm, o);
            sq += __shfl_xor_sync(0xffffffffu, sq, o);
        }
        const float mean = sm * 0.0078125f;
        const float var  = fmaf(-mean, mean, sq * 0.0078125f);
        const float rs   = rsqrtf(var + 1e-5f);
        sdst[r * SZS + lane]      = __float2half_rn(fmaf((v0 - mean) * rs, g0, b0));
        sdst[r * SZS + lane + 32] = __float2half_rn(fmaf((v1 - mean) * rs, g1, b1));
        sdst[r * SZS + lane + 64] = __float2half_rn(fmaf((v2 - mean) * rs, g2, b2));
        sdst[r * SZS + lane + 96] = __float2half_rn(fmaf((v3 - mean) * rs, g3, b3));
    }
}

// 64x128 GEMM: 8 warps in 2(M) x 4(N), warp tile 32x32.
__device__ __forceinline__ void gemmC(
    const __half* sW, const __half* sZ, float acc[2][4][4],
    int wy, int lw, int aRow, int aCol, int bRow, int bCol)
{
    #pragma unroll
    for (int k0 = 0; k0 < 128; k0 += 16) {
        unsigned af[2][4], bf[2][4];
        #pragma unroll
        for (int mt = 0; mt < 2; mt++)
            ldsm4(af[mt], sZ + (wy * 32 + mt * 16 + aRow) * SZS + k0 + aCol);
        #pragma unroll
        for (int p = 0; p < 2; p++)
            ldsm4(bf[p], sW + (lw * 32 + p * 16 + bRow) * SZS + k0 + bCol);
        #pragma unroll
        for (int mt = 0; mt < 2; mt++)
            #pragma unroll
            for (int nt = 0; nt < 4; nt++)
                mma16(acc[mt][nt], af[mt], &bf[nt >> 1][(nt & 1) * 2]);
    }
}

// ---------------- kP: 64-row blocks, 4 GEMM passes + Zn flush ----------------
__global__ __launch_bounds__(256, 2) void kP(
    const float* __restrict__ z,    const float* __restrict__ mask,
    const float* __restrict__ b_ag, const float* __restrict__ b_ap,
    const float* __restrict__ b_bg, const float* __restrict__ b_bp,
    const float* __restrict__ lng,  const float* __restrict__ lnb)
{
    extern __shared__ __half sh[];
    __half* sZ  = sh;                             // [64][SZS]
    __half* sW0 = sh + 64 * SZS;                  // [128][SZS]
    __half* sW1 = sh + 64 * SZS + 128 * SZS;      // [128][SZS]
    __half* sSt = sh + 64 * SZS + 2 * 128 * SZS;  // [64][SZS]
    const int t = threadIdx.x, lane = t & 31, warp = t >> 5;
    const int wy = warp >> 2, lw = warp & 3;
    const int pos0 = blockIdx.x * 64;

    prefW(sW0, d_Wt + 0 * 16384, t);
    lnrows64(z + (size_t)pos0 * 128, sZ, lng, lnb, warp, lane);
    prefW(sW1, d_Wt + 1 * 16384, t);
    __syncthreads();
    // flush LN(z) to d_Znh (natural layout, uint4)
    #pragma unroll
    for (int l = 0; l < 4; l++) {
        const int idx = t + l * 256;              // 1024 uint4
        const int r = idx >> 4, c8 = (idx & 15) * 8;
        *(uint4*)&d_Znh[(size_t)(pos0 + r) * 128 + c8] = *(const uint4*)&sZ[r * SZS + c8];
    }

    const int aRow = (lane & 7) + ((lane >> 3) & 1) * 8;
    const int aCol = (lane >> 4) * 8;
    const int bRow = (lane & 7) + ((lane >> 4) & 1) * 8;
    const int bCol = ((lane >> 3) & 1) * 8;
    const int rB = wy * 32 + (lane >> 2);
    const int cB = lw * 32 + (lane & 3) * 2;

    #pragma unroll 1
    for (int pair = 0; pair < 2; pair++) {
        const float* biasG = pair ? b_bg : b_ag;
        const float* biasP = pair ? b_bp : b_ap;
        __half* plane = pair ? d_Bh : d_Ah;

        float accg[2][4][4] = {};
        CPWAIT(1);
        __syncthreads();
        gemmC(sW0, sZ, accg, wy, lw, aRow, aCol, bRow, bCol);
        __syncthreads();
        if (pair == 0) prefW(sW0, d_Wt + 2 * 16384, t);
        #pragma unroll
        for (int mt = 0; mt < 2; mt++)
            #pragma unroll
            for (int nt = 0; nt < 4; nt++) {
                const int c = cB + nt * 8;
                const float bg0 = biasG[c], bg1 = biasG[c + 1];
                accg[mt][nt][0] = sigf(accg[mt][nt][0] + bg0);
                accg[mt][nt][1] = sigf(accg[mt][nt][1] + bg1);
                accg[mt][nt][2] = sigf(accg[mt][nt][2] + bg0);
                accg[mt][nt][3] = sigf(accg[mt][nt][3] + bg1);
            }

        float accp[2][4][4] = {};
        if (pair == 0) { CPWAIT(1); } else { CPWAIT(0); }
        __syncthreads();
        gemmC(sW1, sZ, accp, wy, lw, aRow, aCol, bRow, bCol);
        __syncthreads();
        if (pair == 0) prefW(sW1, d_Wt + 3 * 16384, t);

        #pragma unroll
        for (int mt = 0; mt < 2; mt++) {
            const int r = rB + mt * 16;
            const float m0 = mask[pos0 + r], m1 = mask[pos0 + r + 8];
            #pragma unroll
            for (int nt = 0; nt < 4; nt++) {
                const int c = cB + nt * 8;
                const float bp0 = biasP[c], bp1 = biasP[c + 1];
                *(__half2*)&sSt[r * SZS + c] = __floats2half2_rn(
                    m0 * accg[mt][nt][0] * (accp[mt][nt][0] + bp0),
                    m0 * accg[mt][nt][1] * (accp[mt][nt][1] + bp1));
                *(__half2*)&sSt[(r + 8) * SZS + c] = __floats2half2_rn(
                    m1 * accg[mt][nt][2] * (accp[mt][nt][2] + bp0),
                    m1 * accg[mt][nt][3] * (accp[mt][nt][3] + bp1));
            }
        }
        __syncthreads();
        #pragma unroll
        for (int l = 0; l < 32; l++) {
            const int idx = t + l * 256;
            const int c = idx >> 6, p = idx & 63;
            plane[(size_t)c * NPOS + pos0 + p] = sSt[p * SZS + c];
        }
        if (pair == 0) __syncthreads();
    }
}

// ---------------- kE: per-channel GEMM, 128x128 tile, 2 CTAs/SM --------------
#define KE_STAGEH 18432                       // halfs per stage: (128+128)*72
#define KE_SMEM   (2 * KE_STAGEH * 2)         // 73728 bytes

__global__ __launch_bounds__(256, 2) void kE()
{
    extern __shared__ __half she[];
    const int t = threadIdx.x, lane = t & 31, warp = t >> 5;
    const int wy = warp >> 2, lw = warp & 3;
    const int j0 = blockIdx.x * 128, i0 = blockIdx.y * 128, ch = blockIdx.z;
    const __half* __restrict__ Ap = d_Ah + (size_t)ch * NPOS;
    const __half* __restrict__ Bp = d_Bh + (size_t)ch * NPOS;

    const int aRow = (lane & 7) + ((lane >> 3) & 1) * 8;
    const int aCol = (lane >> 4) * 8;
    const int bRow = (lane & 7) + ((lane >> 4) & 1) * 8;
    const int bCol = ((lane >> 3) & 1) * 8;

    const int lr = t >> 3, lk8 = (t & 7) * 8;

    auto load_chunk = [&](int c, int stage) {
        __half* sA = she + stage * KE_STAGEH;
        __half* sB = sA + 128 * KES;
        const int kt = c * 64;
        #pragma unroll
        for (int l = 0; l < 4; l++) {
            const int r = lr + l * 32;
            cp16(&sA[r * KES + lk8], &Ap[(size_t)(i0 + r) * 512 + kt + lk8]);
        }
        #pragma unroll
        for (int l = 0; l < 4; l++) {
            const int r = lr + l * 32;
            cp16(&sB[r * KES + lk8], &Bp[(size_t)(j0 + r) * 512 + kt + lk8]);
        }
        CPCOMMIT();
    };

    float acc[4][4][4] = {};

    load_chunk(0, 0);

    #pragma unroll 1
    for (int s = 0; s < 8; s++) {
        if (s < 7) {
            load_chunk(s + 1, (s + 1) & 1);
            CPWAIT(1);
        } else {
            CPWAIT(0);
        }
        __syncthreads();
        const __half* bA = she + (s & 1) * KE_STAGEH;
        const __half* bB = bA + 128 * KES;
        #pragma unroll
        for (int kk = 0; kk < 64; kk += 16) {
            unsigned af[4][4], bf[2][4];
            #pragma unroll
            for (int mt = 0; mt < 4; mt++)
                ldsm4(af[mt], bA + (wy * 64 + mt * 16 + aRow) * KES + kk + aCol);
            #pragma unroll
            for (int p = 0; p < 2; p++)
                ldsm4(bf[p], bB + (lw * 32 + p * 16 + bRow) * KES + kk + bCol);
            #pragma unroll
            for (int mt = 0; mt < 4; mt++)
                #pragma unroll
                for (int nt = 0; nt < 4; nt++)
                    mma16(acc[mt][nt], af[mt], &bf[nt >> 1][(nt & 1) * 2]);
        }
        __syncthreads();
    }

    __half* sSt = she;
    #pragma unroll
    for (int mt = 0; mt < 4; mt++)
        #pragma unroll
        for (int nt = 0; nt < 4; nt++) {
            const int r = wy * 64 + mt * 16 + (lane >> 2);
            const int c = lw * 32 + nt * 8 + (lane & 3) * 2;
            *(__half2*)&sSt[r * SZS + c]       = __floats2half2_rn(acc[mt][nt][0], acc[mt][nt][1]);
            *(__half2*)&sSt[(r + 8) * SZS + c] = __floats2half2_rn(acc[mt][nt][2], acc[mt][nt][3]);
        }
    __syncthreads();
    __half* Xp = d_Xh + (size_t)ch * NPOS;
    #pragma unroll
    for (int l = 0; l < 8; l++) {
        const int idx = t + l * 256;
        const int r = idx >> 4, c16 = idx & 15;
        *(uint4*)&Xp[(size_t)(i0 + r) * 512 + j0 + c16 * 8] = *(const uint4*)&sSt[r * SZS + c16 * 8];
    }
}

// ---------------- kF: fused dual GEMM, gate input from d_Znh -----------------
__global__ __launch_bounds__(256, 3) void kF(
    const float* __restrict__ lnog, const float* __restrict__ lnob,
    const float* __restrict__ b_z,  const float* __restrict__ b_g,
    float* __restrict__ out)
{
    extern __shared__ __half shf[];
    __half* sX = shf;                 // [64][SZS]
    __half* sG = shf + 64 * SZS;      // [64][SZS]
    __half* sW = shf + 128 * SZS;     // [128][SZS]
    const int t = threadIdx.x, lane = t & 31, warp = t >> 5;
    const int wy = warp >> 2, lw = warp & 3;
    const int pos0 = blockIdx.x * 64;
    const int c2 = lane * 2;

    prefW(sW, d_Wt + 4 * 16384, t);   // w_g
    // load LN(z) from d_Znh into sG (async, same group as w_g)
    #pragma unroll
    for (int l = 0; l < 4; l++) {
        const int idx = t + l * 256;              // 1024 uint4
        const int r = idx >> 4, c8 = (idx & 15) * 8;
        cp16(&sG[r * SZS + c8], &d_Znh[(size_t)(pos0 + r) * 128 + c8]);
    }
    CPCOMMIT();

    {
        const int cl = lane >> 2, j = lane & 3;
        const int srow = 8 * (lane >> 3) + (lane & 7);
        #pragma unroll
        for (int it = 0; it < 4; it++) {
            const int tile = warp * 4 + it;
            const int cg = tile >> 1;
            const int pg = tile & 1;
            const __half* src = d_Xh + (size_t)(cg * 8 + cl) * NPOS + pos0 + pg * 32 + 2 * j;
            const unsigned r0 = *(const unsigned*)(src);
            const unsigned r1 = *(const unsigned*)(src + 8);
            const unsigned r2 = *(const unsigned*)(src + 16);
            const unsigned r3 = *(const unsigned*)(src + 24);
            stsm4t(sX + (pg * 32 + srow) * SZS + cg * 8, r0, r1, r2, r3);
        }
    }
    CPWAIT(0);
    __syncthreads();

    const int aRow = (lane & 7) + ((lane >> 3) & 1) * 8;
    const int aCol = (lane >> 4) * 8;
    const int bRow = (lane & 7) + ((lane >> 4) & 1) * 8;
    const int bCol = ((lane >> 3) & 1) * 8;
    const int rB = wy * 32 + (lane >> 2);
    const int cB = lw * 32 + (lane & 3) * 2;

    float accg[2][4][4] = {};
    gemmC(sW, sG, accg, wy, lw, aRow, aCol, bRow, bCol);
    __syncthreads();

    prefW(sW, d_Wt + 5 * 16384, t);   // w_z

    #pragma unroll
    for (int mt = 0; mt < 2; mt++)
        #pragma unroll
        for (int nt = 0; nt < 4; nt++) {
            const int r = rB + mt * 16;
            const int c = cB + nt * 8;
            const float bg0 = b_g[c], bg1 = b_g[c + 1];
            *(__half2*)&sG[r * SZS + c] = __floats2half2_rn(
                sigf(accg[mt][nt][0] + bg0), sigf(accg[mt][nt][1] + bg1));
            *(__half2*)&sG[(r + 8) * SZS + c] = __floats2half2_rn(
                sigf(accg[mt][nt][2] + bg0), sigf(accg[mt][nt][3] + bg1));
        }

    // LN(X) in place
    {
        const float g0 = lnog[c2], g1 = lnog[c2 + 1], g2 = lnog[c2 + 64], g3 = lnog[c2 + 65];
        const float bb0 = lnob[c2], bb1 = lnob[c2 + 1], bb2 = lnob[c2 + 64], bb3 = lnob[c2 + 65];
        #pragma unroll 1
        for (int rr = 0; rr < 8; rr++) {
            const int r = warp * 8 + rr;
            __half* row = sX + r * SZS;
            const float2 v01 = __half22float2(*(__half2*)&row[c2]);
            const float2 v23 = __half22float2(*(__half2*)&row[c2 + 64]);
            float sm = (v01.x + v01.y) + (v23.x + v23.y);
            float sq = fmaf(v01.x, v01.x, fmaf(v01.y, v01.y, fmaf(v23.x, v23.x, v23.y * v23.y)));
            #pragma unroll
            for (int o = 16; o > 0; o >>= 1) {
                sm += __shfl_xor_sync(0xffffffffu, sm, o);
                sq += __shfl_xor_sync(0xffffffffu, sq, o);
            }
            const float mean = sm * 0.0078125f;
            const float var  = fmaf(-mean, mean, sq * 0.0078125f);
            const float rs   = rsqrtf(var + 1e-5f);
            *(__half2*)&row[c2] = __floats2half2_rn(
                fmaf((v01.x - mean) * rs, g0, bb0), fmaf((v01.y - mean) * rs, g1, bb1));
            *(__half2*)&row[c2 + 64] = __floats2half2_rn(
                fmaf((v23.x - mean) * rs, g2, bb2), fmaf((v23.y - mean) * rs, g3, bb3));
        }
    }
    CPWAIT(0);
    __syncthreads();

    float accx[2][4][4] = {};
    gemmC(sW, sX, accx, wy, lw, aRow, aCol, bRow, bCol);

    #pragma unroll
    for (int mt = 0; mt < 2; mt++)
        #pragma unroll
        for (int nt = 0; nt < 4; nt++) {
            const int r = rB + mt * 16;
            const int c0 = cB + nt * 8;
            const float bz0 = b_z[c0], bz1 = b_z[c0 + 1];
            const size_t p0 = (size_t)(pos0 + r) * 128 + c0;
            const size_t p1 = (size_t)(pos0 + r + 8) * 128 + c0;
            const float2 g0 = __half22float2(*(const __half2*)&sG[r * SZS + c0]);
            const float2 g1 = __half22float2(*(const __half2*)&sG[(r + 8) * SZS + c0]);
            *(float2*)&out[p0] = make_float2((accx[mt][nt][0] + bz0) * g0.x,
                                             (accx[mt][nt][1] + bz1) * g0.y);
            *(float2*)&out[p1] = make_float2((accx[mt][nt][2] + bz0) * g1.x,
                                             (accx[mt][nt][3] + bz1) * g1.y);
        }
}

extern "C" void kernel_launch(void* const* d_in, const int* in_sizes, int n_in,
                              void* d_out, int out_size)
{
    const float* z        = (const float*)d_in[0];
    const float* mask     = (const float*)d_in[1];
    const float* w_ag     = (const float*)d_in[2];
    const float* b_ag     = (const float*)d_in[3];
    const float* w_ap     = (const float*)d_in[4];
    const float* b_ap     = (const float*)d_in[5];
    const float* w_bg     = (const float*)d_in[6];
    const float* b_bg     = (const float*)d_in[7];
    const float* w_bp     = (const float*)d_in[8];
    const float* b_bp     = (const float*)d_in[9];
    const float* w_g      = (const float*)d_in[10];
    const float* b_g      = (const float*)d_in[11];
    const float* w_z      = (const float*)d_in[12];
    const float* b_z      = (const float*)d_in[13];
    const float* ln_in_g  = (const float*)d_in[14];
    const float* ln_in_b  = (const float*)d_in[15];
    const float* ln_out_g = (const float*)d_in[16];
    const float* ln_out_b = (const float*)d_in[17];

    const int KP_SMEM = (64 + 2 * 128 + 64) * SZS * 2;   // 104448
    const int KF_SMEM = (64 + 64 + 128) * SZS * 2;       // 69632
    cudaFuncSetAttribute(kP, cudaFuncAttributeMaxDynamicSharedMemorySize, KP_SMEM);
    cudaFuncSetAttribute(kE, cudaFuncAttributeMaxDynamicSharedMemorySize, KE_SMEM);
    cudaFuncSetAttribute(kF, cudaFuncAttributeMaxDynamicSharedMemorySize, KF_SMEM);

    kW<<<6, 256>>>(w_ag, w_ap, w_bg, w_bp, w_g, w_z);
    kP<<<4096, 256, KP_SMEM>>>(z, mask, b_ag, b_ap, b_bg, b_bp, ln_in_g, ln_in_b);
    kE<<<dim3(4, 4, 128), 256, KE_SMEM>>>();
    kF<<<4096, 256, KF_SMEM>>>(ln_out_g, ln_out_b, b_z, b_g, (float*)d_out);
}

// round 16
// speedup vs baseline: 1.2258x; 1.0448x over previous
#include <cuda_runtime.h>
#include <cuda_fp16.h>
#include <cstdint>

// TriangleMultiplicativeUpdate (outgoing), B=1, N=512, C=128. fp16 mma m16n8k16.
// kW: weights -> [n][k] half.
// kP: LN + 4 projections -> half planes via stmatrix.trans epilogue; LN(z) -> d_Znh.
// kE: 128 per-channel GEMMs, 128x128 tiles, 2 CTAs/SM, cp.async double-buffered.
// kF: fused dual GEMM, gate input loaded from d_Znh (no LN recompute).

#define NPOS 262144
#define SZS  136          // smem row stride in halfs
#define KES  72           // kE smem row stride in halfs
#define PST  72           // kP transposed-store row stride in halfs

__device__ __half d_Wt[6 * 16384];           // [w][n][k]
__device__ __half d_Ah[(size_t)128 * NPOS];  // [c][i*512+k]
__device__ __half d_Bh[(size_t)128 * NPOS];
__device__ __half d_Xh[(size_t)128 * NPOS];  // [c][i*512+j]
__device__ __half d_Znh[(size_t)NPOS * 128]; // [pos][c]  LN(z) in half

__device__ __forceinline__ float sigf(float x) { return 1.0f / (1.0f + __expf(-x)); }

__device__ __forceinline__ void mma16(float* d, const unsigned* a, const unsigned* b) {
    asm volatile(
        "mma.sync.aligned.m16n8k16.row.col.f32.f16.f16.f32 "
        "{%0,%1,%2,%3}, {%4,%5,%6,%7}, {%8,%9}, {%0,%1,%2,%3};\n"
        : "+f"(d[0]), "+f"(d[1]), "+f"(d[2]), "+f"(d[3])
        : "r"(a[0]), "r"(a[1]), "r"(a[2]), "r"(a[3]), "r"(b[0]), "r"(b[1]));
}

__device__ __forceinline__ void ldsm4(unsigned* r, const __half* p) {
    unsigned addr = (unsigned)__cvta_generic_to_shared(p);
    asm volatile("ldmatrix.sync.aligned.m8n8.x4.shared.b16 {%0,%1,%2,%3}, [%4];"
                 : "=r"(r[0]), "=r"(r[1]), "=r"(r[2]), "=r"(r[3]) : "r"(addr));
}

__device__ __forceinline__ void stsm4t(__half* p, unsigned r0, unsigned r1,
                                       unsigned r2, unsigned r3) {
    unsigned addr = (unsigned)__cvta_generic_to_shared(p);
    asm volatile("stmatrix.sync.aligned.m8n8.x4.trans.shared.b16 [%0], {%1,%2,%3,%4};"
                 :: "r"(addr), "r"(r0), "r"(r1), "r"(r2), "r"(r3) : "memory");
}

__device__ __forceinline__ void cp16(void* s, const void* g) {
    unsigned sa = (unsigned)__cvta_generic_to_shared(s);
    asm volatile("cp.async.cg.shared.global [%0], [%1], 16;" :: "r"(sa), "l"(g));
}
#define CPCOMMIT() asm volatile("cp.async.commit_group;")
#define CPWAIT(n)  asm volatile("cp.async.wait_group %0;" :: "n"(n))

__device__ __forceinline__ unsigned h2u(__half2 h) { return *(unsigned*)&h; }

// ---------------- kW: weight transpose+convert ------------------------------
__global__ __launch_bounds__(256) void kW(
    const float* __restrict__ w_ag, const float* __restrict__ w_ap,
    const float* __restrict__ w_bg, const float* __restrict__ w_bp,
    const float* __restrict__ w_g,  const float* __restrict__ w_z)
{
    __shared__ float s[128 * 132];
    const float* srcs[6] = {w_ag, w_ap, w_bg, w_bp, w_g, w_z};
    const float* w = srcs[blockIdx.x];
    const int t = threadIdx.x;
    #pragma unroll
    for (int l = 0; l < 64; l++) {
        const int idx = t + l * 256;
        s[(idx >> 7) * 132 + (idx & 127)] = w[idx];   // [k][n]
    }
    __syncthreads();
    __half* dst = d_Wt + blockIdx.x * 16384;
    #pragma unroll
    for (int l = 0; l < 64; l++) {
        const int idx = t + l * 256;                  // idx = n*128 + k
        dst[idx] = __float2half_rn(s[(idx & 127) * 132 + (idx >> 7)]);
    }
}

// ---------------- shared helpers ---------------------------------------------
__device__ __forceinline__ void prefW(__half* buf, const __half* __restrict__ wt, int t) {
    #pragma unroll
    for (int l = 0; l < 8; l++) {
        const int idx = t + l * 256;                 // 2048 uint4
        const int n = idx >> 4, k8 = (idx & 15) * 8;
        cp16(&buf[n * SZS + k8], &wt[n * 128 + k8]);
    }
    CPCOMMIT();
}

__device__ __forceinline__ void lnrows64(const float* __restrict__ zsrc, __half* sdst,
                                         const float* __restrict__ g,
                                         const float* __restrict__ b,
                                         int warp, int lane) {
    const float g0 = g[lane], g1 = g[lane + 32], g2 = g[lane + 64], g3 = g[lane + 96];
    const float b0 = b[lane], b1 = b[lane + 32], b2 = b[lane + 64], b3 = b[lane + 96];
    #pragma unroll 1
    for (int rr = 0; rr < 8; rr++) {
        const int r = warp * 8 + rr;
        const float* zr = zsrc + (size_t)r * 128;
        float v0 = zr[lane], v1 = zr[lane + 32], v2 = zr[lane + 64], v3 = zr[lane + 96];
        float sm = (v0 + v1) + (v2 + v3);
        float sq = fmaf(v0, v0, fmaf(v1, v1, fmaf(v2, v2, v3 * v3)));
        #pragma unroll
        for (int o = 16; o > 0; o >>= 1) {
            sm += __shfl_xor_sync(0xffffffffu, sm, o);
            sq += __shfl_xor_sync(0xffffffffu, sq, o);
        }
        const float mean = sm * 0.0078125f;
        const float var  = fmaf(-mean, mean, sq * 0.0078125f);
        const float rs   = rsqrtf(var + 1e-5f);
        sdst[r * SZS + lane]      = __float2half_rn(fmaf((v0 - mean) * rs, g0, b0));
        sdst[r * SZS + lane + 32] = __float2half_rn(fmaf((v1 - mean) * rs, g1, b1));
        sdst[r * SZS + lane + 64] = __float2half_rn(fmaf((v2 - mean) * rs, g2, b2));
        sdst[r * SZS + lane + 96] = __float2half_rn(fmaf((v3 - mean) * rs, g3, b3));
    }
}

// 64x128 GEMM: 8 warps in 2(M) x 4(N), warp tile 32x32.
__device__ __forceinline__ void gemmC(
    const __half* sW, const __half* sZ, float acc[2][4][4],
    int wy, int lw, int aRow, int aCol, int bRow, int bCol)
{
    #pragma unroll
    for (int k0 = 0; k0 < 128; k0 += 16) {
        unsigned af[2][4], bf[2][4];
        #pragma unroll
        for (int mt = 0; mt < 2; mt++)
            ldsm4(af[mt], sZ + (wy * 32 + mt * 16 + aRow) * SZS + k0 + aCol);
        #pragma unroll
        for (int p = 0; p < 2; p++)
            ldsm4(bf[p], sW + (lw * 32 + p * 16 + bRow) * SZS + k0 + bCol);
        #pragma unroll
        for (int mt = 0; mt < 2; mt++)
            #pragma unroll
            for (int nt = 0; nt < 4; nt++)
                mma16(acc[mt][nt], af[mt], &bf[nt >> 1][(nt & 1) * 2]);
    }
}

// ---------------- kP: 64-row blocks, stmatrix-trans epilogue -----------------
__global__ __launch_bounds__(256, 2) void kP(
    const float* __restrict__ z,    const float* __restrict__ mask,
    const float* __restrict__ b_ag, const float* __restrict__ b_ap,
    const float* __restrict__ b_bg, const float* __restrict__ b_bp,
    const float* __restrict__ lng,  const float* __restrict__ lnb)
{
    extern __shared__ __half sh[];
    __half* sZ  = sh;                             // [64][SZS]
    __half* sW0 = sh + 64 * SZS;                  // [128][SZS]
    __half* sW1 = sh + 64 * SZS + 128 * SZS;      // [128][SZS]
    __half* sT  = sh + 64 * SZS + 2 * 128 * SZS;  // [128][PST] transposed combine
    const int t = threadIdx.x, lane = t & 31, warp = t >> 5;
    const int wy = warp >> 2, lw = warp & 3;
    const int pos0 = blockIdx.x * 64;

    prefW(sW0, d_Wt + 0 * 16384, t);
    lnrows64(z + (size_t)pos0 * 128, sZ, lng, lnb, warp, lane);
    prefW(sW1, d_Wt + 1 * 16384, t);
    __syncthreads();
    // flush LN(z) to d_Znh (natural layout, uint4)
    #pragma unroll
    for (int l = 0; l < 4; l++) {
        const int idx = t + l * 256;              // 1024 uint4
        const int r = idx >> 4, c8 = (idx & 15) * 8;
        *(uint4*)&d_Znh[(size_t)(pos0 + r) * 128 + c8] = *(const uint4*)&sZ[r * SZS + c8];
    }

    const int aRow = (lane & 7) + ((lane >> 3) & 1) * 8;
    const int aCol = (lane >> 4) * 8;
    const int bRow = (lane & 7) + ((lane >> 4) & 1) * 8;
    const int bCol = ((lane >> 3) & 1) * 8;
    const int rB = wy * 32 + (lane >> 2);
    const int cB = lw * 32 + (lane & 3) * 2;
    // stmatrix dest base: lane supplies c-row (lw*32+lane), col = r offset (wy*32)
    __half* stBase = sT + (size_t)(lw * 32 + lane) * PST + wy * 32;

    #pragma unroll 1
    for (int pair = 0; pair < 2; pair++) {
        const float* biasG = pair ? b_bg : b_ag;
        const float* biasP = pair ? b_bp : b_ap;
        __half* plane = pair ? d_Bh : d_Ah;

        float accg[2][4][4] = {};
        CPWAIT(1);
        __syncthreads();
        gemmC(sW0, sZ, accg, wy, lw, aRow, aCol, bRow, bCol);
        __syncthreads();
        if (pair == 0) prefW(sW0, d_Wt + 2 * 16384, t);
        #pragma unroll
        for (int mt = 0; mt < 2; mt++)
            #pragma unroll
            for (int nt = 0; nt < 4; nt++) {
                const int c = cB + nt * 8;
                const float bg0 = biasG[c], bg1 = biasG[c + 1];
                accg[mt][nt][0] = sigf(accg[mt][nt][0] + bg0);
                accg[mt][nt][1] = sigf(accg[mt][nt][1] + bg1);
                accg[mt][nt][2] = sigf(accg[mt][nt][2] + bg0);
                accg[mt][nt][3] = sigf(accg[mt][nt][3] + bg1);
            }

        float accp[2][4][4] = {};
        if (pair == 0) { CPWAIT(1); } else { CPWAIT(0); }
        __syncthreads();
        gemmC(sW1, sZ, accp, wy, lw, aRow, aCol, bRow, bCol);
        __syncthreads();
        if (pair == 0) prefW(sW1, d_Wt + 3 * 16384, t);

        // combine -> stmatrix.trans into sT[c][p]
        #pragma unroll
        for (int mt = 0; mt < 2; mt++) {
            const int r = rB + mt * 16;
            const float m0 = mask[pos0 + r], m1 = mask[pos0 + r + 8];
            unsigned rg0[4], rg1[4];
            #pragma unroll
            for (int nt = 0; nt < 4; nt++) {
                const int c = cB + nt * 8;
                const float bp0 = biasP[c], bp1 = biasP[c + 1];
                rg0[nt] = h2u(__floats2half2_rn(
                    m0 * accg[mt][nt][0] * (accp[mt][nt][0] + bp0),
                    m0 * accg[mt][nt][1] * (accp[mt][nt][1] + bp1)));
                rg1[nt] = h2u(__floats2half2_rn(
                    m1 * accg[mt][nt][2] * (accp[mt][nt][2] + bp0),
                    m1 * accg[mt][nt][3] * (accp[mt][nt][3] + bp1)));
            }
            stsm4t(stBase + mt * 16,     rg0[0], rg0[1], rg0[2], rg0[3]);
            stsm4t(stBase + mt * 16 + 8, rg1[0], rg1[1], rg1[2], rg1[3]);
        }
        __syncthreads();
        // coalesced flush: sT[c][p] -> plane[c][pos0+p], uint4
        #pragma unroll
        for (int l = 0; l < 4; l++) {
            const int idx = t + l * 256;          // 1024 uint4
            const int c = idx >> 3, p8 = (idx & 7) * 8;
            *(uint4*)&plane[(size_t)c * NPOS + pos0 + p8] = *(const uint4*)&sT[c * PST + p8];
        }
        if (pair == 0) __syncthreads();
    }
}

// ---------------- kE: per-channel GEMM, 128x128 tile, 2 CTAs/SM --------------
#define KE_STAGEH 18432                       // halfs per stage: (128+128)*72
#define KE_SMEM   (2 * KE_STAGEH * 2)         // 73728 bytes

__global__ __launch_bounds__(256, 2) void kE()
{
    extern __shared__ __half she[];
    const int t = threadIdx.x, lane = t & 31, warp = t >> 5;
    const int wy = warp >> 2, lw = warp & 3;
    const int j0 = blockIdx.x * 128, i0 = blockIdx.y * 128, ch = blockIdx.z;
    const __half* __restrict__ Ap = d_Ah + (size_t)ch * NPOS;
    const __half* __restrict__ Bp = d_Bh + (size_t)ch * NPOS;

    const int aRow = (lane & 7) + ((lane >> 3) & 1) * 8;
    const int aCol = (lane >> 4) * 8;
    const int bRow = (lane & 7) + ((lane >> 4) & 1) * 8;
    const int bCol = ((lane >> 3) & 1) * 8;

    const int lr = t >> 3, lk8 = (t & 7) * 8;

    auto load_chunk = [&](int c, int stage) {
        __half* sA = she + stage * KE_STAGEH;
        __half* sB = sA + 128 * KES;
        const int kt = c * 64;
        #pragma unroll
        for (int l = 0; l < 4; l++) {
            const int r = lr + l * 32;
            cp16(&sA[r * KES + lk8], &Ap[(size_t)(i0 + r) * 512 + kt + lk8]);
        }
        #pragma unroll
        for (int l = 0; l < 4; l++) {
            const int r = lr + l * 32;
            cp16(&sB[r * KES + lk8], &Bp[(size_t)(j0 + r) * 512 + kt + lk8]);
        }
        CPCOMMIT();
    };

    float acc[4][4][4] = {};

    load_chunk(0, 0);

    #pragma unroll 1
    for (int s = 0; s < 8; s++) {
        if (s < 7) {
            load_chunk(s + 1, (s + 1) & 1);
            CPWAIT(1);
        } else {
            CPWAIT(0);
        }
        __syncthreads();
        const __half* bA = she + (s & 1) * KE_STAGEH;
        const __half* bB = bA + 128 * KES;
        #pragma unroll
        for (int kk = 0; kk < 64; kk += 16) {
            unsigned af[4][4], bf[2][4];
            #pragma unroll
            for (int mt = 0; mt < 4; mt++)
                ldsm4(af[mt], bA + (wy * 64 + mt * 16 + aRow) * KES + kk + aCol);
            #pragma unroll
            for (int p = 0; p < 2; p++)
                ldsm4(bf[p], bB + (lw * 32 + p * 16 + bRow) * KES + kk + bCol);
            #pragma unroll
            for (int mt = 0; mt < 4; mt++)
                #pragma unroll
                for (int nt = 0; nt < 4; nt++)
                    mma16(acc[mt][nt], af[mt], &bf[nt >> 1][(nt & 1) * 2]);
        }
        __syncthreads();
    }

    __half* sSt = she;
    #pragma unroll
    for (int mt = 0; mt < 4; mt++)
        #pragma unroll
        for (int nt = 0; nt < 4; nt++) {
            const int r = wy * 64 + mt * 16 + (lane >> 2);
            const int c = lw * 32 + nt * 8 + (lane & 3) * 2;
            *(__half2*)&sSt[r * SZS + c]       = __floats2half2_rn(acc[mt][nt][0], acc[mt][nt][1]);
            *(__half2*)&sSt[(r + 8) * SZS + c] = __floats2half2_rn(acc[mt][nt][2], acc[mt][nt][3]);
        }
    __syncthreads();
    __half* Xp = d_Xh + (size_t)ch * NPOS;
    #pragma unroll
    for (int l = 0; l < 8; l++) {
        const int idx = t + l * 256;
        const int r = idx >> 4, c16 = idx & 15;
        *(uint4*)&Xp[(size_t)(i0 + r) * 512 + j0 + c16 * 8] = *(const uint4*)&sSt[r * SZS + c16 * 8];
    }
}

// ---------------- kF: fused dual GEMM, gate input from d_Znh -----------------
__global__ __launch_bounds__(256, 3) void kF(
    const float* __restrict__ lnog, const float* __restrict__ lnob,
    const float* __restrict__ b_z,  const float* __restrict__ b_g,
    float* __restrict__ out)
{
    extern __shared__ __half shf[];
    __half* sX = shf;                 // [64][SZS]
    __half* sG = shf + 64 * SZS;      // [64][SZS]
    __half* sW = shf + 128 * SZS;     // [128][SZS]
    const int t = threadIdx.x, lane = t & 31, warp = t >> 5;
    const int wy = warp >> 2, lw = warp & 3;
    const int pos0 = blockIdx.x * 64;
    const int c2 = lane * 2;

    prefW(sW, d_Wt + 4 * 16384, t);   // w_g
    #pragma unroll
    for (int l = 0; l < 4; l++) {
        const int idx = t + l * 256;              // 1024 uint4
        const int r = idx >> 4, c8 = (idx & 15) * 8;
        cp16(&sG[r * SZS + c8], &d_Znh[(size_t)(pos0 + r) * 128 + c8]);
    }
    CPCOMMIT();

    {
        const int cl = lane >> 2, j = lane & 3;
        const int srow = 8 * (lane >> 3) + (lane & 7);
        #pragma unroll
        for (int it = 0; it < 4; it++) {
            const int tile = warp * 4 + it;
            const int cg = tile >> 1;
            const int pg = tile & 1;
            const __half* src = d_Xh + (size_t)(cg * 8 + cl) * NPOS + pos0 + pg * 32 + 2 * j;
            const unsigned r0 = *(const unsigned*)(src);
            const unsigned r1 = *(const unsigned*)(src + 8);
            const unsigned r2 = *(const unsigned*)(src + 16);
            const unsigned r3 = *(const unsigned*)(src + 24);
            stsm4t(sX + (pg * 32 + srow) * SZS + cg * 8, r0, r1, r2, r3);
        }
    }
    CPWAIT(0);
    __syncthreads();

    const int aRow = (lane & 7) + ((lane >> 3) & 1) * 8;
    const int aCol = (lane >> 4) * 8;
    const int bRow = (lane & 7) + ((lane >> 4) & 1) * 8;
    const int bCol = ((lane >> 3) & 1) * 8;
    const int rB = wy * 32 + (lane >> 2);
    const int cB = lw * 32 + (lane & 3) * 2;

    float accg[2][4][4] = {};
    gemmC(sW, sG, accg, wy, lw, aRow, aCol, bRow, bCol);
    __syncthreads();

    prefW(sW, d_Wt + 5 * 16384, t);   // w_z

    #pragma unroll
    for (int mt = 0; mt < 2; mt++)
        #pragma unroll
        for (int nt = 0; nt < 4; nt++) {
            const int r = rB + mt * 16;
            const int c = cB + nt * 8;
            const float bg0 = b_g[c], bg1 = b_g[c + 1];
            *(__half2*)&sG[r * SZS + c] = __floats2half2_rn(
                sigf(accg[mt][nt][0] + bg0), sigf(accg[mt][nt][1] + bg1));
            *(__half2*)&sG[(r + 8) * SZS + c] = __floats2half2_rn(
                sigf(accg[mt][nt][2] + bg0), sigf(accg[mt][nt][3] + bg1));
        }

    // LN(X) in place
    {
        const float g0 = lnog[c2], g1 = lnog[c2 + 1], g2 = lnog[c2 + 64], g3 = lnog[c2 + 65];
        const float bb0 = lnob[c2], bb1 = lnob[c2 + 1], bb2 = lnob[c2 + 64], bb3 = lnob[c2 + 65];
        #pragma unroll 1
        for (int rr = 0; rr < 8; rr++) {
            const int r = warp * 8 + rr;
            __half* row = sX + r * SZS;
            const float2 v01 = __half22float2(*(__half2*)&row[c2]);
            const float2 v23 = __half22float2(*(__half2*)&row[c2 + 64]);
            float sm = (v01.x + v01.y) + (v23.x + v23.y);
            float sq = fmaf(v01.x, v01.x, fmaf(v01.y, v01.y, fmaf(v23.x, v23.x, v23.y * v23.y)));
            #pragma unroll
            for (int o = 16; o > 0; o >>= 1) {
                sm += __shfl_xor_sync(0xffffffffu, sm, o);
                sq += __shfl_xor_sync(0xffffffffu, sq, o);
            }
            const float mean = sm * 0.0078125f;
            const float var  = fmaf(-mean, mean, sq * 0.0078125f);
            const float rs   = rsqrtf(var + 1e-5f);
            *(__half2*)&row[c2] = __floats2half2_rn(
                fmaf((v01.x - mean) * rs, g0, bb0), fmaf((v01.y - mean) * rs, g1, bb1));
            *(__half2*)&row[c2 + 64] = __floats2half2_rn(
                fmaf((v23.x - mean) * rs, g2, bb2), fmaf((v23.y - mean) * rs, g3, bb3));
        }
    }
    CPWAIT(0);
    __syncthreads();

    float accx[2][4][4] = {};
    gemmC(sW, sX, accx, wy, lw, aRow, aCol, bRow, bCol);

    #pragma unroll
    for (int mt = 0; mt < 2; mt++)
        #pragma unroll
        for (int nt = 0; nt < 4; nt++) {
            const int r = rB + mt * 16;
            const int c0 = cB + nt * 8;
            const float bz0 = b_z[c0], bz1 = b_z[c0 + 1];
            const size_t p0 = (size_t)(pos0 + r) * 128 + c0;
            const size_t p1 = (size_t)(pos0 + r + 8) * 128 + c0;
            const float2 g0 = __half22float2(*(const __half2*)&sG[r * SZS + c0]);
            const float2 g1 = __half22float2(*(const __half2*)&sG[(r + 8) * SZS + c0]);
            *(float2*)&out[p0] = make_float2((accx[mt][nt][0] + bz0) * g0.x,
                                             (accx[mt][nt][1] + bz1) * g0.y);
            *(float2*)&out[p1] = make_float2((accx[mt][nt][2] + bz0) * g1.x,
                                             (accx[mt][nt][3] + bz1) * g1.y);
        }
}

extern "C" void kernel_launch(void* const* d_in, const int* in_sizes, int n_in,
                              void* d_out, int out_size)
{
    const float* z        = (const float*)d_in[0];
    const float* mask     = (const float*)d_in[1];
    const float* w_ag     = (const float*)d_in[2];
    const float* b_ag     = (const float*)d_in[3];
    const float* w_ap     = (const float*)d_in[4];
    const float* b_ap     = (const float*)d_in[5];
    const float* w_bg     = (const float*)d_in[6];
    const float* b_bg     = (const float*)d_in[7];
    const float* w_bp     = (const float*)d_in[8];
    const float* b_bp     = (const float*)d_in[9];
    const float* w_g      = (const float*)d_in[10];
    const float* b_g      = (const float*)d_in[11];
    const float* w_z      = (const float*)d_in[12];
    const float* b_z      = (const float*)d_in[13];
    const float* ln_in_g  = (const float*)d_in[14];
    const float* ln_in_b  = (const float*)d_in[15];
    const float* ln_out_g = (const float*)d_in[16];
    const float* ln_out_b = (const float*)d_in[17];

    const int KP_SMEM = (64 * SZS + 2 * 128 * SZS + 128 * PST) * 2;  // 105472
    const int KF_SMEM = (64 + 64 + 128) * SZS * 2;                   // 69632
    cudaFuncSetAttribute(kP, cudaFuncAttributeMaxDynamicSharedMemorySize, KP_SMEM);
    cudaFuncSetAttribute(kE, cudaFuncAttributeMaxDynamicSharedMemorySize, KE_SMEM);
    cudaFuncSetAttribute(kF, cudaFuncAttributeMaxDynamicSharedMemorySize, KF_SMEM);

    kW<<<6, 256>>>(w_ag, w_ap, w_bg, w_bp, w_g, w_z);
    kP<<<4096, 256, KP_SMEM>>>(z, mask, b_ag, b_ap, b_bg, b_bp, ln_in_g, ln_in_b);
    kE<<<dim3(4, 4, 128), 256, KE_SMEM>>>();
    kF<<<4096, 256, KF_SMEM>>>(ln_out_g, ln_out_b, b_z, b_g, (float*)d_out);
}